// round 16
// baseline (speedup 1.0000x reference)
#include <cuda_runtime.h>
#include <math.h>
#include <stdint.h>

// ---------------------------------------------------------------------------
// ASSR reconstruction loss — ONE fused kernel, single pass over pred/target.
//   pix  = mean|pred - target|                  (32,3,512,512)
//   lr   = mean|bicubicAA_down4(pred) - lr_ref| (32,3,128,128)
//   out  = { pix + 0.1*lr, pix, lr, lr, 0 }
//
// Bicubic AA (a=-0.75), scale=4, align_corners=False: identical 16-tap
// window everywhere (raw sum = 4.0 exactly); replicate border folds into
// rows/cols 0 and 511 (closed-form sums WA..WD).
//
// R16: cp.async (LDGSTS) deep pipeline — MLP decoupled from registers.
// 5-stage smem ring of (pred,tgt) 4-row groups, ~48 KB in flight per block;
// compute reads smem. 288 blocks (43/43/42 rows) x 512 thr = exactly
// 2 blocks/SM, 32 warps/SM, single perfectly balanced wave.
// ---------------------------------------------------------------------------

#define HW       512
#define OUTHW    128
#define NBC      96
#define SPLITS   3               // row tiles: 43, 43, 42
#define THREADS  512
#define NBLOCKS  (SPLITS * NBC)  // 288
#define DEPTH    5               // cp.async stage ring
#define VROWS    8               // vertical-result ring rows
#define STAGE_F  4096            // floats per stage: pred 4*512 + tgt 4*512
#define VOFF     (DEPTH * STAGE_F)            // 20480 floats
#define SMEM_FLOATS (VOFF + VROWS * HW)       // 24576
#define SMEM_BYTES  (SMEM_FLOATS * 4)         // 98304

// normalized taps (raw cubic values are dyadic; raw window sum = 4.0 exactly)
#define WT0 (-0.0025634765625f)
#define WT1 (-0.0164794921875f)
#define WT2 (-0.0274658203125f)
#define WT3 (-0.0179443359375f)
#define WT4 ( 0.0286865234375f)
#define WT5 ( 0.1065673828125f)
#define WT6 ( 0.1873779296875f)
#define WT7 ( 0.2418212890625f)
// border-folded sums (replicate clamp)
#define WA  ( 0.2581787109375f)  // sum wt[0..6]
#define WB  (-0.0465087890625f)  // sum wt[0..2]
#define WC  WB                   // sum wt[13..15] (symmetry)
#define WD  WA                   // sum wt[9..15]

__constant__ float c_wt[16] = {WT0,WT1,WT2,WT3,WT4,WT5,WT6,WT7,
                               WT7,WT6,WT5,WT4,WT3,WT2,WT1,WT0};

__device__ double g_pp[NBLOCKS];
__device__ double g_pl[NBLOCKS];
__device__ unsigned int g_count;   // zero-init; last block resets to 0

__device__ __forceinline__ void cp16(uint32_t sdst, const float* gsrc) {
    asm volatile("cp.async.cg.shared.global [%0], [%1], 16;\n"
                 :: "r"(sdst), "l"(gsrc));
}
#define CPCOMMIT() asm volatile("cp.async.commit_group;\n" ::)
#define CPWAIT3()  asm volatile("cp.async.wait_group 3;\n" :: : "memory")

// horizontal FIR over first NR rows of the 8-row vrows ring + |.-lr_ref|
// 512 threads: ow = t&127, r0 = t>>7 (0..3), rows r0 and r0+4.
template<int NR>
__device__ __forceinline__ float horiz_chunk(const float* __restrict__ vrows,
                                             const float* __restrict__ lrb,
                                             int t)
{
    float lrs = 0.f;
    const int ow = t & (OUTHW - 1);
    const int r0 = t >> 7;
    if (ow >= 2 && ow < OUTHW - 2) {
        #pragma unroll
        for (int i = 0; i < 2; ++i) {
            const int rr = r0 + 4 * i;
            if (rr < NR) {
                const float4* v =
                    reinterpret_cast<const float4*>(vrows + rr * HW) + (ow - 2);
                const float4 a = v[0], b = v[1], c = v[2], d = v[3], e = v[4];
                float acc = a.z * WT0 + a.w * WT1
                          + b.x * WT2 + b.y * WT3 + b.z * WT4 + b.w * WT5
                          + c.x * WT6 + c.y * WT7 + c.z * WT7 + c.w * WT6
                          + d.x * WT5 + d.y * WT4 + d.z * WT3 + d.w * WT2
                          + e.x * WT1 + e.y * WT0;
                lrs += fabsf(acc - __ldcs(&lrb[rr * OUTHW]));
            }
        }
    } else {
        for (int i = 0; i < 2; ++i) {
            const int rr = r0 + 4 * i;
            if (rr < NR) {
                const float* row = vrows + rr * HW;
                float acc = 0.f;
                #pragma unroll
                for (int tt = 0; tt < 16; ++tt) {
                    int src = 4 * ow - 6 + tt;
                    src = src < 0 ? 0 : (src > HW - 1 ? HW - 1 : src);
                    acc += c_wt[tt] * row[src];
                }
                lrs += fabsf(acc - __ldcs(&lrb[rr * OUTHW]));
            }
        }
    }
    return lrs;
}

// cp.async-pipelined vertical polyphase FIR + pix + chunked horizontal.
// Group kk (0..CHAINR+3) = real group oh0-2+kk, input rows 4k..4k+3.
// Stage ring depth 5: group g lives in stage g%5. Each iteration: issue
// group kk+3, commit, wait_group 3 (group kk complete), barrier, compute
// group kk from smem. Stage reuse distance 5 + the per-iteration barrier
// make the WAR hazard impossible.
template<int CHAINR, bool FIRST, bool LAST>
__device__ __forceinline__ void process_block(const float* __restrict__ Pg,
                                              const float* __restrict__ Tg,
                                              const float* __restrict__ lr0,
                                              const int t,
                                              float* __restrict__ sm,
                                              uint32_t smb,
                                              float& pixs, float& lrs)
{
    constexpr int NGROUPS = CHAINR + 4;
    constexpr int FULLC   = CHAINR / 8;        // full 8-row chunks (=5)
    constexpr int REM     = CHAINR - 8 * FULLC;

    const int r_ld = t >> 7;                   // 0..3: row of group loaded
    const int c16  = t & 127;                  // 16B chunk within row
    const int ldof = r_ld * HW + c16 * 4;      // float offset in group
    const uint32_t sdst0 = smb + (uint32_t)((r_ld * 512 + c16 * 4) * 4);
    float* vrows = sm + VOFF;

    float A0 = 0.f, A1 = 0.f, A2 = 0.f, A3 = 0.f, A4 = 0.f;

    #define GVALID(kk_) ((!FIRST || (kk_) >= 2) && \
                         ((kk_) <= (LAST ? CHAINR + 1 : CHAINR + 3)))
    #define GCORE(kk_)  ((kk_) >= 2 && (kk_) < 2 + CHAINR)
    #define GOFF(kk_)   ((FIRST ? ((kk_) - 2) : (kk_)) * (4 * HW))
    // issue one group's cp.asyncs (pred always-if-valid, tgt only if core);
    // ALWAYS commit so the group count is uniform across splits.
    #define ISSUE(kk_) do {                                                   \
        if ((kk_) < NGROUPS && GVALID(kk_)) {                                 \
            const int off = GOFF(kk_);                                        \
            const uint32_t sd = sdst0 +                                       \
                (uint32_t)(((kk_) % DEPTH) * STAGE_F * 4);                    \
            cp16(sd, Pg + off + ldof);                                        \
            if (GCORE(kk_))                                                   \
                cp16(sd + 2048 * 4, Tg + off + ldof);                         \
        }                                                                     \
        CPCOMMIT();                                                           \
    } while (0)

    ISSUE(0);
    ISSUE(1);
    ISSUE(2);

    #pragma unroll
    for (int kk = 0; kk < NGROUPS; ++kk) {
        ISSUE(kk + 3);
        CPWAIT3();                      // group kk landed in stage kk%DEPTH
        __syncthreads();                // visible block-wide; prev compute done

        const float* SP = sm + (kk % DEPTH) * STAGE_F;   // pred rows [4][512]
        const float* ST = SP + 2048;                     // tgt rows  [4][512]

        if (GVALID(kk)) {
            const float p0 = SP[t];
            const float p1 = SP[512 + t];
            const float p2 = SP[1024 + t];
            const float p3 = SP[1536 + t];
            if (GCORE(kk)) {
                pixs += fabsf(p0 - ST[t])        + fabsf(p1 - ST[512 + t])
                      + fabsf(p2 - ST[1024 + t]) + fabsf(p3 - ST[1536 + t]);
            }
            // phase r=0 (input row 4k): taps 14,10,6,2 -> oh k-2..k+1
            if (FIRST && kk == 2) {          // input row 0 border fold
                A2 += WA * p0; A3 += WB * p0;
            } else {
                A0 += WT1 * p0; A1 += WT5 * p0;
                A2 += WT6 * p0; A3 += WT2 * p0;
            }
            // phase r=1: taps 15,11,7,3 -> oh k-2..k+1
            A0 += WT0 * p1; A1 += WT4 * p1;
            A2 += WT7 * p1; A3 += WT3 * p1;
            // phase r=2: taps 12,8,4,0 -> oh k-1..k+2
            A1 += WT3 * p2; A2 += WT7 * p2;
            A3 += WT4 * p2; A4 += WT0 * p2;
            // phase r=3: taps 13,9,5,1 -> oh k-1..k+2
            if (LAST && kk == CHAINR + 1) {  // input row 511 border fold
                A1 += WC * p3; A2 += WD * p3;
            } else {
                A1 += WT2 * p3; A2 += WT6 * p3;
                A3 += WT5 * p3; A4 += WT1 * p3;
            }
        }
        if (kk >= 4)                          // output row kk-4 complete
            vrows[((kk - 4) & (VROWS - 1)) * HW + t] = A0;

        A0 = A1; A1 = A2; A2 = A3; A3 = A4; A4 = 0.f;

        // 8-row chunk c complete after kk = 8c+11 (c = 0..FULLC-1)
        if (kk >= 11 && ((kk - 11) & 7) == 0 && (kk - 11) / 8 < FULLC) {
            const int c = (kk - 11) / 8;
            __syncthreads();                  // all vrows rows of chunk done
            lrs += horiz_chunk<VROWS>(vrows, lr0 + c * 8 * OUTHW, t);
        }
    }
    __syncthreads();
    lrs += horiz_chunk<REM>(vrows, lr0 + FULLC * 8 * OUTHW, t);
    #undef ISSUE
    #undef GOFF
    #undef GCORE
    #undef GVALID
}

__global__ __launch_bounds__(THREADS, 2)
void assr_fused_kernel(const float* __restrict__ pred,
                       const float* __restrict__ tgt,
                       const float* __restrict__ lrr,
                       float* __restrict__ out, int out_size)
{
    extern __shared__ float sm[];          // 96 KB: 5 stages + 8-row vrows
    __shared__ float  red[32];
    __shared__ double dred[32];
    __shared__ unsigned sh_last;

    const int t   = threadIdx.x;
    const int s   = blockIdx.x;              // 0..2
    const int bc  = blockIdx.y;              // 0..95
    const int oh0 = (s == 0) ? 0 : (s == 1 ? 43 : 86);

    const uint32_t smb = (uint32_t)__cvta_generic_to_shared(sm);

    // base at first group this block touches (group oh0-2, clamped to 0)
    const int g0 = (s == 0) ? 0 : (oh0 - 2);
    const float* Pg = pred + (size_t)bc * (HW * HW) + (size_t)(4 * g0) * HW;
    const float* Tg = tgt  + (size_t)bc * (HW * HW) + (size_t)(4 * g0) * HW;
    const float* lr0 = lrr + (size_t)bc * (OUTHW * OUTHW)
                           + (size_t)oh0 * OUTHW + (t & (OUTHW - 1));

    float pixs = 0.f, lrs = 0.f;

    if (s == 0)
        process_block<43, true , false>(Pg, Tg, lr0, t, sm, smb, pixs, lrs);
    else if (s == 1)
        process_block<43, false, false>(Pg, Tg, lr0, t, sm, smb, pixs, lrs);
    else
        process_block<42, false, true >(Pg, Tg, lr0, t, sm, smb, pixs, lrs);

    // ---------------- block reduction -> per-block partial slot ------------
    #pragma unroll
    for (int o = 16; o; o >>= 1) {
        pixs += __shfl_xor_sync(0xffffffffu, pixs, o);
        lrs  += __shfl_xor_sync(0xffffffffu, lrs,  o);
    }
    const int wid = t >> 5, lane = t & 31;
    if (lane == 0) { red[wid] = pixs; red[16 + wid] = lrs; }
    __syncthreads();
    if (t == 0) {
        double ps = 0.0, ls = 0.0;
        #pragma unroll
        for (int i = 0; i < THREADS / 32; ++i) {
            ps += (double)red[i];
            ls += (double)red[16 + i];
        }
        const int slot = bc * SPLITS + s;
        g_pp[slot] = ps;
        g_pl[slot] = ls;
        __threadfence();
        const unsigned old = atomicAdd(&g_count, 1u);
        sh_last = (old == NBLOCKS - 1) ? 1u : 0u;
    }
    __syncthreads();

    // ---------------- last block finalizes ---------------------------------
    if (sh_last) {
        double p = 0.0, l = 0.0;
        if (t < NBLOCKS) {                   // 288 slots, 512 threads
            p = __ldcg(&g_pp[t]);
            l = __ldcg(&g_pl[t]);
        }
        #pragma unroll
        for (int o = 16; o; o >>= 1) {
            p += __shfl_xor_sync(0xffffffffu, p, o);
            l += __shfl_xor_sync(0xffffffffu, l, o);
        }
        if (lane == 0) { dred[wid] = p; dred[16 + wid] = l; }
        __syncthreads();
        if (t == 0) {
            double ps = 0.0, ls = 0.0;
            #pragma unroll
            for (int i = 0; i < THREADS / 32; ++i) {
                ps += dred[i];
                ls += dred[16 + i];
            }
            const double pix     = ps / 25165824.0;   // 32*3*512*512
            const double lr      = ls / 1572864.0;    // 32*3*128*128
            const double consist = lr;                 // LAM_LR*lr + 0
            const double total   = pix + 0.1 * consist;
            float vals[5] = {(float)total, (float)pix, (float)consist,
                             (float)lr, 0.f};
            for (int i = 0; i < out_size; ++i)
                out[i] = (i < 5) ? vals[i] : 0.f;
            g_count = 0;           // reset for next launch (deterministic)
        }
    }
}

extern "C" void kernel_launch(void* const* d_in, const int* in_sizes, int n_in,
                              void* d_out, int out_size)
{
    const float* pred = (const float*)d_in[0];
    const float* tgt  = (const float*)d_in[1];
    const float* lrr  = (const float*)d_in[2];
    // d_in[3] (scale) is uniform 4.0 -> static sizes, unused.

    cudaFuncSetAttribute(assr_fused_kernel,
                         cudaFuncAttributeMaxDynamicSharedMemorySize,
                         SMEM_BYTES);

    const dim3 grid(SPLITS, NBC);
    assr_fused_kernel<<<grid, THREADS, SMEM_BYTES>>>(pred, tgt, lrr,
                                                     (float*)d_out, out_size);
}

// round 17
// speedup vs baseline: 1.2192x; 1.2192x over previous
#include <cuda_runtime.h>
#include <math.h>

// ---------------------------------------------------------------------------
// ASSR reconstruction loss — ONE fused kernel, single pass over pred/target.
//   pix  = mean|pred - target|                  (32,3,512,512)
//   lr   = mean|bicubicAA_down4(pred) - lr_ref| (32,3,128,128)
//   out  = { pix + 0.1*lr, pix, lr, lr, 0 }
//
// Bicubic AA (a=-0.75), scale=4, align_corners=False: identical 16-tap
// window everywhere (raw sum = 4.0 exactly); replicate border folds into
// rows/cols 0 and 511 (closed-form sums WA..WD).
//
// FINAL (== R10 champion, 39.0us): 384 blocks x 256 threads (float2/thread),
// branch-free <FIRST,LAST> unrolled polyphase vertical FIR with pred
// software-pipeline depth 2 + tgt 2-slot register rotation, 16-row smem ring,
// horizontal FIR via conflict-free LDS.128, single-kernel last-block-done
// reduction. Measured at the machine's effective ~4.8 TB/s ceiling moving
// the analytic minimum traffic (~215 MB) — bandwidth-optimal.
// ---------------------------------------------------------------------------

#define HW       512
#define OUTHW    128
#define NBC      96             // 32 batch * 3 channels
#define CHAIN    32             // output rows per block (two 16-row chunks)
#define SPLITS   (OUTHW / CHAIN) // 4
#define BUF      16             // smem row buffer (one chunk)
#define THREADS  256            // each thread owns 2 columns (float2)
#define NBLOCKS  (SPLITS * NBC) // 384
#define RS       (HW / 2)       // row stride in float2
#define NGROUPS  (CHAIN + 4)    // 36 pipeline iterations

// normalized taps (raw cubic values are dyadic; raw window sum = 4.0 exactly)
#define WT0 (-0.0025634765625f)
#define WT1 (-0.0164794921875f)
#define WT2 (-0.0274658203125f)
#define WT3 (-0.0179443359375f)
#define WT4 ( 0.0286865234375f)
#define WT5 ( 0.1065673828125f)
#define WT6 ( 0.1873779296875f)
#define WT7 ( 0.2418212890625f)
// border-folded sums (replicate clamp)
#define WA  ( 0.2581787109375f)  // sum wt[0..6]
#define WB  (-0.0465087890625f)  // sum wt[0..2]
#define WC  WB                   // sum wt[13..15] (symmetry)
#define WD  WA                   // sum wt[9..15]

__constant__ float c_wt[16] = {WT0,WT1,WT2,WT3,WT4,WT5,WT6,WT7,
                               WT7,WT6,WT5,WT4,WT3,WT2,WT1,WT0};

__device__ double g_pp[NBLOCKS];
__device__ double g_pl[NBLOCKS];
__device__ unsigned int g_count;   // zero-init; last block resets to 0

__device__ __forceinline__ void fma2(float2& a, float w, const float2& v) {
    a.x += w * v.x; a.y += w * v.y;
}
__device__ __forceinline__ float ad2(const float2& a, const float2& b) {
    return fabsf(a.x - b.x) + fabsf(a.y - b.y);
}

// horizontal FIR over one 16-row chunk in smem + |.-lr_ref| partial
__device__ __forceinline__ float horiz_chunk(const float* __restrict__ vrows,
                                             const float* __restrict__ lrb,
                                             int t)
{
    float lrs = 0.f;
    const int ow = t & (OUTHW - 1);
    const int r0 = t >> 7;                   // 0..1; rows r0, r0+2, ..., r0+14
    if (ow >= 2 && ow < OUTHW - 2) {
        #pragma unroll
        for (int i = 0; i < BUF / 2; ++i) {
            const int rr = r0 + 2 * i;
            const float4* v =
                reinterpret_cast<const float4*>(vrows + rr * HW) + (ow - 2);
            const float4 a = v[0], b = v[1], c = v[2], d = v[3], e = v[4];
            float acc = a.z * WT0 + a.w * WT1
                      + b.x * WT2 + b.y * WT3 + b.z * WT4 + b.w * WT5
                      + c.x * WT6 + c.y * WT7 + c.z * WT7 + c.w * WT6
                      + d.x * WT5 + d.y * WT4 + d.z * WT3 + d.w * WT2
                      + e.x * WT1 + e.y * WT0;
            lrs += fabsf(acc - __ldcs(&lrb[rr * OUTHW]));
        }
    } else {
        for (int i = 0; i < BUF / 2; ++i) {
            const int rr = r0 + 2 * i;
            const float* row = vrows + rr * HW;
            float acc = 0.f;
            #pragma unroll
            for (int tt = 0; tt < 16; ++tt) {
                int src = 4 * ow - 6 + tt;
                src = src < 0 ? 0 : (src > HW - 1 ? HW - 1 : src);
                acc += c_wt[tt] * row[src];
            }
            lrs += fabsf(acc - __ldcs(&lrb[rr * OUTHW]));
        }
    }
    return lrs;
}

// Vertical polyphase FIR + pix + both horizontal chunks, software-pipelined.
// Group kk (0..35) = group oh0-2+kk, reads input rows 4k..4k+3.
// Pred pipeline: A=kk (compute), B=kk+1 (in flight), C=kk+2 (just issued).
// Tgt: 2-slot rotation; slot (kk+1)&1 loaded during kk, consumed at kk+1.
template<bool FIRST, bool LAST>
__device__ __forceinline__ void process_block(const float2* __restrict__ P2,
                                              const int tdiff,
                                              const float* __restrict__ lr0,
                                              const int t,
                                              float* __restrict__ vrows,
                                              float& pixs, float& lrs)
{
    float2 A[4], B[4], C[4], Ts[2][4];
    #pragma unroll
    for (int i = 0; i < 4; ++i) {
        A[i].x=0.f;A[i].y=0.f; B[i].x=0.f;B[i].y=0.f;
        C[i].x=0.f;C[i].y=0.f;
        Ts[0][i].x=0.f;Ts[0][i].y=0.f;
        Ts[1][i].x=0.f;Ts[1][i].y=0.f;
    }
    float2 A0={0,0}, A1={0,0}, A2={0,0}, A3={0,0}, A4={0,0};

    #define GVALID(kk_) ((!FIRST || (kk_) >= 2) && ((kk_) <= (LAST ? 33 : 35)))
    #define GOFF(kk_)   ((FIRST ? ((kk_) - 2) : (kk_)) * (4 * RS))
    #define PLOAD(dst, kk_) do {                                              \
        if (GVALID(kk_)) {                                                    \
            const float2* pp = P2 + GOFF(kk_);                                \
            dst[0] = pp[0]; dst[1] = pp[RS];                                  \
            dst[2] = pp[2*RS]; dst[3] = pp[3*RS];                             \
        } } while (0)
    #define TLOAD(dst, kk_) do {                                              \
        if ((kk_) >= 2 && (kk_) < 2 + CHAIN) {                                \
            const float2* tp = P2 + GOFF(kk_) + tdiff;                        \
            dst[0] = __ldcs(tp);          dst[1] = __ldcs(tp + RS);           \
            dst[2] = __ldcs(tp + 2 * RS); dst[3] = __ldcs(tp + 3 * RS);       \
        } } while (0)

    PLOAD(A, 0);
    PLOAD(B, 1);

    #pragma unroll
    for (int kk = 0; kk < NGROUPS; ++kk) {
        // issue pred group kk+2 and tgt group kk+1 BEFORE computing kk
        PLOAD(C, kk + 2);
        TLOAD(Ts[(kk + 1) & 1], kk + 1);

        const bool core  = (kk >= 2) && (kk < 2 + CHAIN);
        const bool valid = GVALID(kk);
        if (valid) {
            if (core) {
                const float2* T = Ts[kk & 1];
                pixs += ad2(A[0], T[0]) + ad2(A[1], T[1])
                      + ad2(A[2], T[2]) + ad2(A[3], T[3]);
            }
            // phase r=0 (input row 4k): taps 14,10,6,2 -> oh k-2..k+1
            if (FIRST && kk == 2) {          // input row 0 border fold
                fma2(A2, WA, A[0]); fma2(A3, WB, A[0]);
            } else {
                fma2(A0, WT1, A[0]); fma2(A1, WT5, A[0]);
                fma2(A2, WT6, A[0]); fma2(A3, WT2, A[0]);
            }
            // phase r=1: taps 15,11,7,3 -> oh k-2..k+1
            fma2(A0, WT0, A[1]); fma2(A1, WT4, A[1]);
            fma2(A2, WT7, A[1]); fma2(A3, WT3, A[1]);
            // phase r=2: taps 12,8,4,0 -> oh k-1..k+2
            fma2(A1, WT3, A[2]); fma2(A2, WT7, A[2]);
            fma2(A3, WT4, A[2]); fma2(A4, WT0, A[2]);
            // phase r=3: taps 13,9,5,1 -> oh k-1..k+2
            if (LAST && kk == 33) {          // input row 511 border fold
                fma2(A1, WC, A[3]); fma2(A2, WD, A[3]);
            } else {
                fma2(A1, WT2, A[3]); fma2(A2, WT6, A[3]);
                fma2(A3, WT5, A[3]); fma2(A4, WT1, A[3]);
            }
        }
        if (kk >= 4) {                       // output row kk-4 complete
            reinterpret_cast<float2*>(
                vrows + ((kk - 4) & (BUF - 1)) * HW)[t] = A0;
        }
        // roll accumulators and pipeline buffers (renamed under full unroll)
        A0 = A1; A1 = A2; A2 = A3; A3 = A4; A4.x = 0.f; A4.y = 0.f;
        #pragma unroll
        for (int i = 0; i < 4; ++i) { A[i] = B[i]; B[i] = C[i]; }

        // chunk boundary: rows 0..15 ready after kk=19
        if (kk == 19) {
            __syncthreads();
            lrs += horiz_chunk(vrows, lr0, t);
            __syncthreads();
        }
    }
    __syncthreads();
    lrs += horiz_chunk(vrows, lr0 + BUF * OUTHW, t);
    #undef PLOAD
    #undef TLOAD
    #undef GOFF
    #undef GVALID
}

__global__ __launch_bounds__(THREADS, 3)
void assr_fused_kernel(const float* __restrict__ pred,
                       const float* __restrict__ tgt,
                       const float* __restrict__ lrr,
                       float* __restrict__ out, int out_size)
{
    __shared__ float  vrows[BUF * HW];     // 32 KB chunk buffer
    __shared__ float  red[16];
    __shared__ double dred[16];
    __shared__ unsigned sh_last;

    const int t   = threadIdx.x;            // owns columns 2t, 2t+1
    const int s   = blockIdx.x;              // 0..3
    const int bc  = blockIdx.y;              // 0..95
    const int oh0 = CHAIN * s;

    // base at first group this block touches (group oh0-2, clamped to 0)
    const int g0 = (s == 0) ? 0 : (oh0 - 2);
    const float2* P2 =
        reinterpret_cast<const float2*>(pred + (size_t)bc * (HW * HW))
        + (size_t)(4 * g0) * RS + t;
    const int tdiff = (int)(reinterpret_cast<const float2*>(tgt)
                          - reinterpret_cast<const float2*>(pred));
    const float* lr0 = lrr + (size_t)bc * (OUTHW * OUTHW)
                           + (size_t)oh0 * OUTHW + (t & (OUTHW - 1));

    float pixs = 0.f, lrs = 0.f;

    if (s == 0)
        process_block<true , false>(P2, tdiff, lr0, t, vrows, pixs, lrs);
    else if (s == SPLITS - 1)
        process_block<false, true >(P2, tdiff, lr0, t, vrows, pixs, lrs);
    else
        process_block<false, false>(P2, tdiff, lr0, t, vrows, pixs, lrs);

    // ---------------- block reduction -> per-block partial slot ------------
    #pragma unroll
    for (int o = 16; o; o >>= 1) {
        pixs += __shfl_xor_sync(0xffffffffu, pixs, o);
        lrs  += __shfl_xor_sync(0xffffffffu, lrs,  o);
    }
    const int wid = t >> 5, lane = t & 31;
    if (lane == 0) { red[wid] = pixs; red[8 + wid] = lrs; }
    __syncthreads();
    if (t == 0) {
        double ps = 0.0, ls = 0.0;
        #pragma unroll
        for (int i = 0; i < THREADS / 32; ++i) {
            ps += (double)red[i];
            ls += (double)red[8 + i];
        }
        const int slot = bc * SPLITS + s;
        g_pp[slot] = ps;
        g_pl[slot] = ls;
        __threadfence();
        const unsigned old = atomicAdd(&g_count, 1u);
        sh_last = (old == NBLOCKS - 1) ? 1u : 0u;
    }
    __syncthreads();

    // ---------------- last block finalizes ---------------------------------
    if (sh_last) {
        double p = 0.0, l = 0.0;
        #pragma unroll
        for (int i = 0; i < 2; ++i) {        // 384 slots, 256 threads
            const int idx = t + THREADS * i;
            if (idx < NBLOCKS) {
                p += __ldcg(&g_pp[idx]);
                l += __ldcg(&g_pl[idx]);
            }
        }
        #pragma unroll
        for (int o = 16; o; o >>= 1) {
            p += __shfl_xor_sync(0xffffffffu, p, o);
            l += __shfl_xor_sync(0xffffffffu, l, o);
        }
        if (lane == 0) { dred[wid] = p; dred[8 + wid] = l; }
        __syncthreads();
        if (t == 0) {
            double ps = 0.0, ls = 0.0;
            #pragma unroll
            for (int i = 0; i < THREADS / 32; ++i) {
                ps += dred[i];
                ls += dred[8 + i];
            }
            const double pix     = ps / 25165824.0;   // 32*3*512*512
            const double lr      = ls / 1572864.0;    // 32*3*128*128
            const double consist = lr;                 // LAM_LR*lr + 0
            const double total   = pix + 0.1 * consist;
            float vals[5] = {(float)total, (float)pix, (float)consist,
                             (float)lr, 0.f};
            for (int i = 0; i < out_size; ++i)
                out[i] = (i < 5) ? vals[i] : 0.f;
            g_count = 0;           // reset for next launch (deterministic)
        }
    }
}

extern "C" void kernel_launch(void* const* d_in, const int* in_sizes, int n_in,
                              void* d_out, int out_size)
{
    const float* pred = (const float*)d_in[0];
    const float* tgt  = (const float*)d_in[1];
    const float* lrr  = (const float*)d_in[2];
    // d_in[3] (scale) is uniform 4.0 -> static sizes, unused.

    const dim3 grid(SPLITS, NBC);
    assr_fused_kernel<<<grid, THREADS>>>(pred, tgt, lrr,
                                         (float*)d_out, out_size);
}